// round 11
// baseline (speedup 1.0000x reference)
#include <cuda_runtime.h>
#include <cuda_fp16.h>
#include <cstdint>

#define BATCH 32768
#define EMB   256
#define NVEC  4096
#define KNN   20
#define MARGIN_F 0.08f

#define M_TILE 128
#define BN     64            // N chunk
#define KC     64            // K chunk (halves)
#define N_CHUNKS (NVEC / BN)           // 64
#define K_CHUNKS (EMB / KC)            // 4
#define STAGES   (N_CHUNKS * K_CHUNKS) // 256

#define STRIDE_A 264         // halves per A row
#define STRIDE_B 72          // halves per B row

// smem offsets (bytes)
#define OFF_AH 0
#define OFF_B  (M_TILE * STRIDE_A * 2)                    // 67584
#define BBUF_SZ (BN * STRIDE_B * 2)                       // 9216
#define OFF_BH(buf) (OFF_B + (buf) * BBUF_SZ)
#define OFF_RED (OFF_B + 2 * BBUF_SZ)
#define SMEM_BYTES (OFF_RED + 4096)

// device scratch
__device__ int    g_ix[BATCH];
__device__ int    g_nflag;
__device__ int    g_list[BATCH];
__device__ __half gXh[BATCH * EMB];
__device__ __half gWh[NVEC * EMB];

// ---------------------------------------------------------------------------
__device__ __forceinline__ uint32_t smem_u32(const void* p) {
    uint32_t a;
    asm("{ .reg .u64 t; cvta.to.shared.u64 t, %1; cvt.u32.u64 %0, t; }" : "=r"(a) : "l"(p));
    return a;
}
#define CP_ASYNC16(dst, src) \
    asm volatile("cp.async.cg.shared.global [%0], [%1], 16;" :: "r"(dst), "l"(src) : "memory")
#define CP_COMMIT() asm volatile("cp.async.commit_group;" ::: "memory")
#define CP_WAIT1()  asm volatile("cp.async.wait_group 1;" ::: "memory")
#define CP_WAIT0()  asm volatile("cp.async.wait_group 0;" ::: "memory")

#define LDMATRIX_X4(r0, r1, r2, r3, a) \
    asm volatile("ldmatrix.sync.aligned.m8n8.x4.shared.b16 {%0,%1,%2,%3}, [%4];" \
                 : "=r"(r0), "=r"(r1), "=r"(r2), "=r"(r3) : "r"(a))

#define MMA16816(c, a0, a1, a2, a3, b0, b1)                                      \
    asm volatile("mma.sync.aligned.m16n8k16.row.col.f32.f16.f16.f32 "            \
                 "{%0,%1,%2,%3}, {%4,%5,%6,%7}, {%8,%9}, {%0,%1,%2,%3};"         \
                 : "+f"((c)[0]), "+f"((c)[1]), "+f"((c)[2]), "+f"((c)[3])        \
                 : "r"(a0), "r"(a1), "r"(a2), "r"(a3), "r"(b0), "r"(b1))

// ordering with index tie-break (lowest index wins on equal value)
__device__ __forceinline__ bool lt2(float v, int i, float w, int j) {
    return v < w || (v == w && i < j);
}
__device__ __forceinline__ void upd2(float v, int n, float& v1, int& i1,
                                     float& v2, int& i2) {
    if (lt2(v, n, v1, i1)) { v2 = v1; i2 = i1; v1 = v; i1 = n; }
    else if (lt2(v, n, v2, i2)) { v2 = v; i2 = n; }
}
__device__ __forceinline__ void merge2(float b1, int bi1, float b2, int bi2,
                                       float& a1, int& ai1, float& a2, int& ai2) {
    if (lt2(b1, bi1, a1, ai1)) {
        float n2; int n2i;
        if (lt2(a1, ai1, b2, bi2)) { n2 = a1; n2i = ai1; } else { n2 = b2; n2i = bi2; }
        a1 = b1; ai1 = bi1; a2 = n2; ai2 = n2i;
    } else if (lt2(b1, bi1, a2, ai2)) {
        a2 = b1; ai2 = bi1;
    }
}

// authoritative distance: STRICTLY SEQUENTIAL fp32 FMA over k=0..255 with a
// single accumulator — proven (R7) to reproduce the reference argmin decision.
__device__ __forceinline__ float seqdot(const float* __restrict__ xr,
                                        const float* __restrict__ wr) {
    float d = 0.f;
    #pragma unroll 8
    for (int k = 0; k < EMB; k++) d = fmaf(xr[k], wr[k], d);
    return d;
}

// ---------------------------------------------------------------------------
// Kernel R: reset flag counter
// ---------------------------------------------------------------------------
__global__ void reset_kernel() {
    if (threadIdx.x == 0) g_nflag = 0;
}

// ---------------------------------------------------------------------------
// Kernel 0: fp16 conversion of x and W (hi only — candidate-generation pass)
// ---------------------------------------------------------------------------
__global__ void __launch_bounds__(256)
split_fp16_kernel(const float* __restrict__ x, const float* __restrict__ W) {
    int t = blockIdx.x * blockDim.x + threadIdx.x;
    int stride = gridDim.x * blockDim.x;
    const float4* x4 = (const float4*)x;
    const float4* w4 = (const float4*)W;
    for (int i = t; i < BATCH * EMB / 4; i += stride) {
        float4 v = x4[i];
        ((__half2*)gXh)[i * 2]     = __halves2half2(__float2half_rn(v.x), __float2half_rn(v.y));
        ((__half2*)gXh)[i * 2 + 1] = __halves2half2(__float2half_rn(v.z), __float2half_rn(v.w));
    }
    for (int i = t; i < NVEC * EMB / 4; i += stride) {
        float4 v = w4[i];
        ((__half2*)gWh)[i * 2]     = __halves2half2(__float2half_rn(v.x), __float2half_rn(v.y));
        ((__half2*)gWh)[i * 2 + 1] = __halves2half2(__float2half_rn(v.z), __float2half_rn(v.w));
    }
}

// ---------------------------------------------------------------------------
// Kernel 1: single-pass fp16 GEMM (dist ~= x . W^T) with fused top-2 + margin.
// 256 thr, warp grid 4(m) x 2(n); warp tile 32x32.
// Rows whose approx top-2 gap < MARGIN_F are flagged for exact fullscan.
// ---------------------------------------------------------------------------
extern __shared__ char dsm[];

__global__ void __launch_bounds__(256, 1)
gemm_topk_kernel() {
    const int tid  = threadIdx.x;
    const int lane = tid & 31;
    const int wid  = tid >> 5;
    const int wm   = wid >> 1;          // 0..3
    const int wn   = wid & 1;           // 0..1
    const int m0   = blockIdx.x * M_TILE;

    const uint32_t sb = smem_u32(dsm);

    // ---- resident A load (hi, 128 rows x 256 halves) ----
    #pragma unroll
    for (int i = 0; i < 16; i++) {
        int idx = tid + i * 256;
        int row = idx >> 5, seg = idx & 31;
        uint32_t off = (uint32_t)(row * STRIDE_A + seg * 8) * 2;
        CP_ASYNC16(sb + OFF_AH + off, gXh + (size_t)(m0 + row) * EMB + seg * 8);
    }
    // ---- prefetch stage 0 B ----
    #pragma unroll
    for (int i = 0; i < 2; i++) {
        int idx = tid + i * 256;
        int row = idx >> 3, seg = idx & 7;
        uint32_t off = (uint32_t)(row * STRIDE_B + seg * 8) * 2;
        CP_ASYNC16(sb + OFF_BH(0) + off, gWh + (size_t)row * EMB + seg * 8);
    }
    CP_COMMIT();

    const int arow  = (lane & 7) + ((lane >> 3) & 1) * 8;
    const int akoff = (lane >> 4) * 8;
    const int brow  = (lane & 7) + (lane >> 4) * 8;
    const int bkoff = ((lane >> 3) & 1) * 8;

    float acc[2][4][4];
    float mv1[4], mv2[4];
    int   mi1[4], mi2[4];
    #pragma unroll
    for (int r = 0; r < 4; r++) {
        mv1[r] = 3.4e38f; mi1[r] = 0x7FFFFFFF;
        mv2[r] = 3.4e38f; mi2[r] = 0x7FFFFFFF;
    }

    for (int s = 0; s < STAGES; s++) {
        const int nc = s >> 2, kc = s & 3;
        const int buf = s & 1;

        if (s + 1 < STAGES) {
            const int nn = (s + 1) >> 2, nk = (s + 1) & 3;
            const int nb = (s + 1) & 1;
            #pragma unroll
            for (int i = 0; i < 2; i++) {
                int idx = tid + i * 256;
                int row = idx >> 3, seg = idx & 7;
                uint32_t off = (uint32_t)(row * STRIDE_B + seg * 8) * 2;
                const size_t src = (size_t)(nn * BN + row) * EMB + nk * KC + seg * 8;
                CP_ASYNC16(sb + OFF_BH(nb) + off, gWh + src);
            }
            CP_COMMIT();
            CP_WAIT1();
        } else {
            CP_WAIT0();
        }
        __syncthreads();

        if (kc == 0) {
            #pragma unroll
            for (int mf = 0; mf < 2; mf++)
                #pragma unroll
                for (int nf = 0; nf < 4; nf++)
                    #pragma unroll
                    for (int j = 0; j < 4; j++) acc[mf][nf][j] = 0.f;
        }

        #pragma unroll
        for (int k16 = 0; k16 < 4; k16++) {
            const int kgA = kc * KC + k16 * 16;
            uint32_t ah[2][4], bh[2][4];
            #pragma unroll
            for (int mf = 0; mf < 2; mf++) {
                uint32_t aoff = (uint32_t)((wm * 32 + mf * 16 + arow) * STRIDE_A
                                           + kgA + akoff) * 2;
                LDMATRIX_X4(ah[mf][0], ah[mf][1], ah[mf][2], ah[mf][3], sb + OFF_AH + aoff);
            }
            #pragma unroll
            for (int g = 0; g < 2; g++) {
                uint32_t boff = (uint32_t)((wn * 32 + g * 16 + brow) * STRIDE_B
                                           + k16 * 16 + bkoff) * 2;
                LDMATRIX_X4(bh[g][0], bh[g][1], bh[g][2], bh[g][3], sb + OFF_BH(buf) + boff);
            }
            #pragma unroll
            for (int mf = 0; mf < 2; mf++) {
                #pragma unroll
                for (int nf = 0; nf < 4; nf++) {
                    const int g = nf >> 1, h = (nf & 1) * 2;
                    MMA16816(acc[mf][nf], ah[mf][0], ah[mf][1], ah[mf][2], ah[mf][3],
                             bh[g][h], bh[g][h + 1]);
                }
            }
        }

        // ---- N-chunk done: fused per-thread top-2 update ----
        if (kc == 3) {
            const int nbase = nc * BN + wn * 32 + (lane & 3) * 2;
            #pragma unroll
            for (int mf = 0; mf < 2; mf++) {
                #pragma unroll
                for (int half = 0; half < 2; half++) {
                    const int slot = mf * 2 + half;
                    #pragma unroll
                    for (int nf = 0; nf < 4; nf++) {
                        float v0 = acc[mf][nf][half * 2];
                        float v1 = acc[mf][nf][half * 2 + 1];
                        int n = nbase + nf * 8;
                        upd2(v0, n,     mv1[slot], mi1[slot], mv2[slot], mi2[slot]);
                        upd2(v1, n + 1, mv1[slot], mi1[slot], mv2[slot], mi2[slot]);
                    }
                }
            }
        }
        __syncthreads();   // protect B buffer reuse
    }

    // ---- reduce top-2: quad shuffle, then across warp_n via smem ----
    #pragma unroll
    for (int d = 1; d < 4; d <<= 1) {
        #pragma unroll
        for (int slot = 0; slot < 4; slot++) {
            float ov1 = __shfl_xor_sync(0xFFFFFFFF, mv1[slot], d);
            int   oi1 = __shfl_xor_sync(0xFFFFFFFF, mi1[slot], d);
            float ov2 = __shfl_xor_sync(0xFFFFFFFF, mv2[slot], d);
            int   oi2 = __shfl_xor_sync(0xFFFFFFFF, mi2[slot], d);
            merge2(ov1, oi1, ov2, oi2, mv1[slot], mi1[slot], mv2[slot], mi2[slot]);
        }
    }
    float* sv1 = (float*)(dsm + OFF_RED);                 // [2][128] each
    int*   si1 = (int*)  (dsm + OFF_RED + 1024);
    float* sv2 = (float*)(dsm + OFF_RED + 2048);
    int*   si2 = (int*)  (dsm + OFF_RED + 3072);
    if ((lane & 3) == 0) {
        #pragma unroll
        for (int slot = 0; slot < 4; slot++) {
            const int mf = slot >> 1, half = slot & 1;
            const int row = wm * 32 + mf * 16 + half * 8 + (lane >> 2);
            sv1[wn * 128 + row] = mv1[slot];
            si1[wn * 128 + row] = mi1[slot];
            sv2[wn * 128 + row] = mv2[slot];
            si2[wn * 128 + row] = mi2[slot];
        }
    }
    __syncthreads();
    if (tid < 128) {
        float a1 = sv1[tid], a2 = sv2[tid];
        int   b1 = si1[tid], b2 = si2[tid];
        merge2(sv1[128 + tid], si1[128 + tid], sv2[128 + tid], si2[128 + tid],
               a1, b1, a2, b2);
        const int row = m0 + tid;
        if (a2 - a1 > MARGIN_F) {
            g_ix[row] = b1;             // certified winner
        } else {
            g_ix[row] = b1;             // provisional; fullscan overrides
            int pos = atomicAdd(&g_nflag, 1);
            g_list[pos] = row;
        }
    }
}

// ---------------------------------------------------------------------------
// Kernel 2: full sequential-FMA argmin scan for flagged rows.
// ---------------------------------------------------------------------------
__global__ void __launch_bounds__(256)
fullscan_kernel(const float* __restrict__ x, const float* __restrict__ W) {
    __shared__ float sx[EMB];
    __shared__ float sval[256];
    __shared__ int   sidx[256];
    const int tid = threadIdx.x;

    for (int j = blockIdx.x; j < g_nflag; j += gridDim.x) {
        const int b = g_list[j];
        if (tid < EMB) sx[tid] = x[(size_t)b * EMB + tid];
        __syncthreads();

        float bv = 3.4e38f;
        int   bi = 0x7FFFFFFF;
        for (int n = tid; n < NVEC; n += 256) {
            float d = seqdot(sx, W + (size_t)n * EMB);
            if (lt2(d, n, bv, bi)) { bv = d; bi = n; }
        }
        sval[tid] = bv; sidx[tid] = bi;
        __syncthreads();
        for (int st = 128; st; st >>= 1) {
            if (tid < st) {
                if (lt2(sval[tid + st], sidx[tid + st], sval[tid], sidx[tid])) {
                    sval[tid] = sval[tid + st]; sidx[tid] = sidx[tid + st];
                }
            }
            __syncthreads();
        }
        if (tid == 0) g_ix[b] = sidx[0];
        __syncthreads();
    }
}

// ---------------------------------------------------------------------------
// Kernel 3: Gaussian-weighted neighbor gather. One warp per batch row.
// ---------------------------------------------------------------------------
__global__ void __launch_bounds__(256)
wknn_gather_kernel(const float* __restrict__ W, float* __restrict__ out) {
    const int lane = threadIdx.x & 31;
    const int warp = threadIdx.x >> 5;
    const int b    = blockIdx.x * 8 + warp;

    const int ix = g_ix[b];
    const bool left_edge = (ix < KNN);

    float4 a0 = {0.f, 0.f, 0.f, 0.f};
    float4 a1 = {0.f, 0.f, 0.f, 0.f};
    float wsum = 0.f;

    #pragma unroll
    for (int j = 0; j <= 2 * KNN; j++) {
        const int o = j - KNN;
        const int idx = ix + o;
        bool valid = (idx >= 0) && (idx < NVEC) && !(left_edge && (o == KNN));
        if (valid) {
            const float g = expf(-0.5f * (float)(o * o));
            wsum += g;
            const float4* wr = (const float4*)(W + (size_t)idx * EMB) + lane * 2;
            float4 v0 = wr[0];
            float4 v1 = wr[1];
            a0.x += g * v0.x; a0.y += g * v0.y; a0.z += g * v0.z; a0.w += g * v0.w;
            a1.x += g * v1.x; a1.y += g * v1.y; a1.z += g * v1.z; a1.w += g * v1.w;
        }
    }

    const float inv = 1.0f / wsum;
    a0.x *= inv; a0.y *= inv; a0.z *= inv; a0.w *= inv;
    a1.x *= inv; a1.y *= inv; a1.z *= inv; a1.w *= inv;

    float4* op = (float4*)(out + (size_t)b * EMB) + lane * 2;
    op[0] = a0;
    op[1] = a1;
}

// ---------------------------------------------------------------------------
extern "C" void kernel_launch(void* const* d_in, const int* in_sizes, int n_in,
                              void* d_out, int out_size) {
    const float* x;
    const float* W;
    if (in_sizes[0] == BATCH * EMB) { x = (const float*)d_in[0]; W = (const float*)d_in[1]; }
    else                            { x = (const float*)d_in[1]; W = (const float*)d_in[0]; }
    float* out = (float*)d_out;

    cudaFuncSetAttribute(gemm_topk_kernel,
                         cudaFuncAttributeMaxDynamicSharedMemorySize, SMEM_BYTES);

    reset_kernel<<<1, 32>>>();
    split_fp16_kernel<<<2048, 256>>>(x, W);
    gemm_topk_kernel<<<BATCH / M_TILE, 256, SMEM_BYTES>>>();
    fullscan_kernel<<<256, 256>>>(x, W);
    wknn_gather_kernel<<<BATCH / 8, 256>>>(W, out);
}